// round 1
// baseline (speedup 1.0000x reference)
#include <cuda_runtime.h>
#include <cstdint>

#define N_NODES 100000
#define IN_C    128
#define HID_C   64
#define OUT_C   32

// ---------------- scratch (static device globals; no allocation) ----------
__device__ float g_dinv[N_NODES];                      // deg -> rsqrt(deg)
__device__ float g_h1[(size_t)N_NODES * HID_C];        // x @ W1
__device__ float g_o1[(size_t)N_NODES * HID_C];        // aggregated layer-1 (pre-relu)
__device__ float g_h2[(size_t)N_NODES * OUT_C];        // relu(o1) @ W2

// ---------------- degree / norm ----------------
__global__ void k_init_deg() {
    int i = blockIdx.x * blockDim.x + threadIdx.x;
    if (i < N_NODES) g_dinv[i] = 1.0f;   // self loop contributes 1
}

__global__ void k_deg(const int* __restrict__ dst, int E) {
    int i = blockIdx.x * blockDim.x + threadIdx.x;
    if (i < E) atomicAdd(&g_dinv[dst[i]], 1.0f);
}

__global__ void k_rsqrt() {
    int i = blockIdx.x * blockDim.x + threadIdx.x;
    if (i < N_NODES) g_dinv[i] = rsqrtf(g_dinv[i]);   // deg >= 1 always
}

// ---------------- GEMM1: h1[N,64] = x[N,128] @ W1[128,64] ----------------
// Block: 256 threads, 32 rows per block. smem: x tile 16KB + full W1 32KB = 48KB.
__global__ void __launch_bounds__(256) k_gemm1(const float* __restrict__ x,
                                               const float* __restrict__ W) {
    __shared__ float xs[32 * 128];
    __shared__ float ws[128 * 64];
    const int tid  = threadIdx.x;
    const int row0 = blockIdx.x * 32;

    // load W1 (8192 floats = 2048 float4)
    const float4* Wv  = (const float4*)W;
    float4*       wsv = (float4*)ws;
#pragma unroll
    for (int i = 0; i < 8; ++i) wsv[tid + i * 256] = Wv[tid + i * 256];

    // load x tile (contiguous 32x128 chunk = 1024 float4)
    const float4* xv  = (const float4*)(x + (size_t)row0 * IN_C);
    float4*       xsv = (float4*)xs;
#pragma unroll
    for (int i = 0; i < 4; ++i) xsv[tid + i * 256] = xv[tid + i * 256];
    __syncthreads();

    const int tx = tid & 15;       // 16 col groups -> col = tx*4
    const int ty = tid >> 4;       // 16 row groups -> rows ty*2, ty*2+1
    const int c  = tx * 4;
    float acc[2][4] = {};
#pragma unroll 4
    for (int k = 0; k < 128; ++k) {
        float4 b = *(const float4*)&ws[k * 64 + c];
#pragma unroll
        for (int i = 0; i < 2; ++i) {
            float a = xs[(ty * 2 + i) * 128 + k];
            acc[i][0] += a * b.x; acc[i][1] += a * b.y;
            acc[i][2] += a * b.z; acc[i][3] += a * b.w;
        }
    }
#pragma unroll
    for (int i = 0; i < 2; ++i) {
        int r = row0 + ty * 2 + i;
        *(float4*)&g_h1[(size_t)r * HID_C + c] =
            make_float4(acc[i][0], acc[i][1], acc[i][2], acc[i][3]);
    }
}

// ---------------- self-loop init layer 1: o1 = b1 + h1 * dinv^2 ----------
__global__ void k_self1(const float* __restrict__ b1) {
    int i = blockIdx.x * blockDim.x + threadIdx.x;   // over N*64/4 float4s
    if (i >= N_NODES * HID_C / 4) return;
    int node = i >> 4;
    float d  = g_dinv[node];
    float dd = d * d;
    float4 h  = ((const float4*)g_h1)[i];
    float4 bb = ((const float4*)b1)[i & 15];
    ((float4*)g_o1)[i] = make_float4(bb.x + h.x * dd, bb.y + h.y * dd,
                                     bb.z + h.z * dd, bb.w + h.w * dd);
}

// ---------------- edge scatter layer 1 (16 threads/edge, float4 RED) -----
__global__ void k_scat1(const int* __restrict__ src, const int* __restrict__ dst, int E) {
    int t = blockIdx.x * blockDim.x + threadIdx.x;
    if (t >= E * 16) return;
    int e  = t >> 4;
    int c4 = (t & 15) << 2;
    int s = src[e];
    int d = dst[e];
    float w = g_dinv[s] * g_dinv[d];
    float4 v = *(const float4*)&g_h1[(size_t)s * HID_C + c4];
    float* p = &g_o1[(size_t)d * HID_C + c4];
    asm volatile("red.global.add.v4.f32 [%0], {%1,%2,%3,%4};"
                 :: "l"(p), "f"(v.x * w), "f"(v.y * w), "f"(v.z * w), "f"(v.w * w)
                 : "memory");
}

// ---------------- GEMM2: h2[N,32] = relu(o1)[N,64] @ W2[64,32] -----------
// Block: 256 threads, 64 rows. smem: x tile 16KB + W2 8KB.
__global__ void __launch_bounds__(256) k_gemm2(const float* __restrict__ W) {
    __shared__ float xs[64 * 64];
    __shared__ float ws[64 * 32];
    const int tid  = threadIdx.x;
    const int row0 = blockIdx.x * 64;

    const float4* Wv  = (const float4*)W;       // 2048 floats = 512 float4
    float4*       wsv = (float4*)ws;
#pragma unroll
    for (int i = 0; i < 2; ++i) wsv[tid + i * 256] = Wv[tid + i * 256];

    int nrows = N_NODES - row0; if (nrows > 64) nrows = 64;
    const float4* xv  = (const float4*)(g_o1 + (size_t)row0 * HID_C);
    float4*       xsv = (float4*)xs;
    for (int i = tid; i < nrows * 16; i += 256) {
        float4 v = xv[i];
        v.x = fmaxf(v.x, 0.f); v.y = fmaxf(v.y, 0.f);
        v.z = fmaxf(v.z, 0.f); v.w = fmaxf(v.w, 0.f);
        xsv[i] = v;
    }
    __syncthreads();

    const int tx = tid & 7;        // col = tx*4 (8*4 = 32)
    const int ty = tid >> 3;       // 32 groups -> rows ty*2, ty*2+1
    const int c  = tx * 4;
    float acc[2][4] = {};
#pragma unroll 4
    for (int k = 0; k < 64; ++k) {
        float4 b = *(const float4*)&ws[k * 32 + c];
#pragma unroll
        for (int i = 0; i < 2; ++i) {
            float a = xs[(ty * 2 + i) * 64 + k];
            acc[i][0] += a * b.x; acc[i][1] += a * b.y;
            acc[i][2] += a * b.z; acc[i][3] += a * b.w;
        }
    }
#pragma unroll
    for (int i = 0; i < 2; ++i) {
        int r = row0 + ty * 2 + i;
        if (r < N_NODES)
            *(float4*)&g_h2[(size_t)r * OUT_C + c] =
                make_float4(acc[i][0], acc[i][1], acc[i][2], acc[i][3]);
    }
}

// ---------------- self-loop init layer 2: out = b2 + h2 * dinv^2 ---------
__global__ void k_self2(const float* __restrict__ b2, float* __restrict__ out) {
    int i = blockIdx.x * blockDim.x + threadIdx.x;   // over N*32/4 float4s
    if (i >= N_NODES * OUT_C / 4) return;
    int node = i >> 3;
    float d  = g_dinv[node];
    float dd = d * d;
    float4 h  = ((const float4*)g_h2)[i];
    float4 bb = ((const float4*)b2)[i & 7];
    ((float4*)out)[i] = make_float4(bb.x + h.x * dd, bb.y + h.y * dd,
                                    bb.z + h.z * dd, bb.w + h.w * dd);
}

// ---------------- edge scatter layer 2 (8 threads/edge) ------------------
__global__ void k_scat2(const int* __restrict__ src, const int* __restrict__ dst,
                        int E, float* __restrict__ out) {
    int t = blockIdx.x * blockDim.x + threadIdx.x;
    if (t >= E * 8) return;
    int e  = t >> 3;
    int c4 = (t & 7) << 2;
    int s = src[e];
    int d = dst[e];
    float w = g_dinv[s] * g_dinv[d];
    float4 v = *(const float4*)&g_h2[(size_t)s * OUT_C + c4];
    float* p = &out[(size_t)d * OUT_C + c4];
    asm volatile("red.global.add.v4.f32 [%0], {%1,%2,%3,%4};"
                 :: "l"(p), "f"(v.x * w), "f"(v.y * w), "f"(v.z * w), "f"(v.w * w)
                 : "memory");
}

// ---------------- launch -------------------------------------------------
extern "C" void kernel_launch(void* const* d_in, const int* in_sizes, int n_in,
                              void* d_out, int out_size) {
    const float* x  = (const float*)d_in[0];
    const int*   ei = (const int*)  d_in[1];
    const float* W1 = (const float*)d_in[2];
    const float* b1 = (const float*)d_in[3];
    const float* W2 = (const float*)d_in[4];
    const float* b2 = (const float*)d_in[5];
    float*       out = (float*)d_out;

    const int E   = in_sizes[1] / 2;
    const int* src = ei;
    const int* dst = ei + E;

    k_init_deg<<<(N_NODES + 255) / 256, 256>>>();
    k_deg<<<(E + 255) / 256, 256>>>(dst, E);
    k_rsqrt<<<(N_NODES + 255) / 256, 256>>>();

    k_gemm1<<<N_NODES / 32, 256>>>(x, W1);                      // 100000 % 32 == 0
    k_self1<<<(N_NODES * HID_C / 4 + 255) / 256, 256>>>(b1);
    k_scat1<<<(E * 16 + 255) / 256, 256>>>(src, dst, E);

    k_gemm2<<<(N_NODES + 63) / 64, 256>>>(W2);
    k_self2<<<(N_NODES * OUT_C / 4 + 255) / 256, 256>>>(b2, out);
    k_scat2<<<(E * 8 + 255) / 256, 256>>>(src, dst, E, out);
}

// round 2
// speedup vs baseline: 1.2750x; 1.2750x over previous
#include <cuda_runtime.h>
#include <cstdint>

#define N_NODES 100000
#define IN_C    128
#define HID_C   64
#define OUT_C   32
#define E_MAX   1600000
#define NB_SCAN ((N_NODES + 255) / 256)   // 391

// ---------------- scratch ----------------
__device__ float g_dinv[N_NODES];
__device__ int   g_cnt[N_NODES];
__device__ int   g_rp[N_NODES + 1];     // CSR rowptr (by dst)
__device__ int   g_wptr[N_NODES];       // fill cursors
__device__ int   g_bsum[NB_SCAN];       // block sums for scan
__device__ float2 g_epk[E_MAX];         // packed (src_as_float_bits, weight)
__device__ float g_h1[(size_t)N_NODES * HID_C];
__device__ float g_o1[(size_t)N_NODES * HID_C];
__device__ float g_h2[(size_t)N_NODES * OUT_C];

// ---------------- degree / norm / CSR ----------------
__global__ void k_zero() {
    int i = blockIdx.x * blockDim.x + threadIdx.x;
    if (i < N_NODES) g_cnt[i] = 0;
}

__global__ void k_count(const int* __restrict__ dst, int E) {
    int i = blockIdx.x * blockDim.x + threadIdx.x;
    if (i < E) atomicAdd(&g_cnt[dst[i]], 1);
}

__global__ void k_dinv() {
    int i = blockIdx.x * blockDim.x + threadIdx.x;
    if (i < N_NODES) g_dinv[i] = rsqrtf(1.0f + (float)g_cnt[i]);
}

// block-level inclusive scan; writes per-element exclusive prefix + block total
__global__ void k_scan1() {
    __shared__ int sh[256];
    int t = threadIdx.x;
    int i = blockIdx.x * 256 + t;
    int v = (i < N_NODES) ? g_cnt[i] : 0;
    sh[t] = v;
    __syncthreads();
#pragma unroll
    for (int off = 1; off < 256; off <<= 1) {
        int x = (t >= off) ? sh[t - off] : 0;
        __syncthreads();
        sh[t] += x;
        __syncthreads();
    }
    if (i < N_NODES) g_rp[i] = sh[t] - v;          // exclusive within block
    if (t == 255) g_bsum[blockIdx.x] = sh[255];
}

// scan the 391 block sums (single block)
__global__ void k_scan2() {
    __shared__ int sh[512];
    int t = threadIdx.x;
    int v = (t < NB_SCAN) ? g_bsum[t] : 0;
    sh[t] = v;
    __syncthreads();
#pragma unroll
    for (int off = 1; off < 512; off <<= 1) {
        int x = (t >= off) ? sh[t - off] : 0;
        __syncthreads();
        sh[t] += x;
        __syncthreads();
    }
    if (t < NB_SCAN) g_bsum[t] = sh[t] - v;        // exclusive
}

__global__ void k_scan3(int E) {
    int i = blockIdx.x * blockDim.x + threadIdx.x;
    if (i < N_NODES) {
        int v = g_rp[i] + g_bsum[i >> 8];
        g_rp[i]   = v;
        g_wptr[i] = v;
    }
    if (i == 0) g_rp[N_NODES] = E;
}

__global__ void k_fill(const int* __restrict__ src, const int* __restrict__ dst, int E) {
    int e = blockIdx.x * blockDim.x + threadIdx.x;
    if (e >= E) return;
    int s = src[e], d = dst[e];
    int pos = atomicAdd(&g_wptr[d], 1);
    g_epk[pos] = make_float2(__int_as_float(s), g_dinv[s] * g_dinv[d]);
}

// ---------------- GEMM1: h1[N,64] = x[N,128] @ W1[128,64], f32x2 FFMA2 ----
// 256 threads, tile M=128 x N=64, K in 4 chunks of 32.
// per thread: 4 rows x 8 cols; A transposed in smem for float4 loads.
#define XT_STRIDE 132
__global__ void __launch_bounds__(256) k_gemm1(const float* __restrict__ x,
                                               const float* __restrict__ W) {
    __shared__ float xs_t[32 * XT_STRIDE];   // [k][row], padded
    __shared__ float ws[32 * 64];            // [k][col]
    const int t    = threadIdx.x;
    const int row0 = blockIdx.x * 128;
    const int tx8  = (t & 7) * 8;
    const int ty4  = (t >> 3) * 4;

    unsigned long long acc[4][4];            // [row][colpair] packed f32x2
#pragma unroll
    for (int r = 0; r < 4; ++r)
#pragma unroll
        for (int j = 0; j < 4; ++j) acc[r][j] = 0ull;

    for (int kc = 0; kc < 128; kc += 32) {
        __syncthreads();
        // load W chunk: rows kc..kc+31 of [128][64] -> 512 float4
        {
            const float4* Wv = (const float4*)(W + kc * 64);
            float4* wsv = (float4*)ws;
            wsv[t]       = Wv[t];
            wsv[t + 256] = Wv[t + 256];
        }
        // load x chunk transposed: 128 rows x 32 k -> 1024 float4 reads
#pragma unroll
        for (int i = 0; i < 4; ++i) {
            int idx = t + i * 256;           // 0..1023
            int r = idx >> 3;                // 0..127
            int q = idx & 7;                 // k-group
            float4 v;
            if (row0 + r < N_NODES)
                v = *(const float4*)(x + (size_t)(row0 + r) * IN_C + kc + q * 4);
            else
                v = make_float4(0.f, 0.f, 0.f, 0.f);
            xs_t[(q * 4 + 0) * XT_STRIDE + r] = v.x;
            xs_t[(q * 4 + 1) * XT_STRIDE + r] = v.y;
            xs_t[(q * 4 + 2) * XT_STRIDE + r] = v.z;
            xs_t[(q * 4 + 3) * XT_STRIDE + r] = v.w;
        }
        __syncthreads();

#pragma unroll 8
        for (int k = 0; k < 32; ++k) {
            float4 av = *(const float4*)&xs_t[k * XT_STRIDE + ty4];
            ulonglong2 b0 = *(const ulonglong2*)&ws[k * 64 + tx8];
            ulonglong2 b1 = *(const ulonglong2*)&ws[k * 64 + tx8 + 4];
            unsigned long long pa[4];
            asm("mov.b64 %0, {%1,%1};" : "=l"(pa[0]) : "f"(av.x));
            asm("mov.b64 %0, {%1,%1};" : "=l"(pa[1]) : "f"(av.y));
            asm("mov.b64 %0, {%1,%1};" : "=l"(pa[2]) : "f"(av.z));
            asm("mov.b64 %0, {%1,%1};" : "=l"(pa[3]) : "f"(av.w));
#pragma unroll
            for (int r = 0; r < 4; ++r) {
                asm("fma.rn.f32x2 %0, %1, %2, %0;" : "+l"(acc[r][0]) : "l"(pa[r]), "l"(b0.x));
                asm("fma.rn.f32x2 %0, %1, %2, %0;" : "+l"(acc[r][1]) : "l"(pa[r]), "l"(b0.y));
                asm("fma.rn.f32x2 %0, %1, %2, %0;" : "+l"(acc[r][2]) : "l"(pa[r]), "l"(b1.x));
                asm("fma.rn.f32x2 %0, %1, %2, %0;" : "+l"(acc[r][3]) : "l"(pa[r]), "l"(b1.y));
            }
        }
    }

#pragma unroll
    for (int r = 0; r < 4; ++r) {
        int row = row0 + ty4 + r;
        if (row < N_NODES) {
            float o[8];
#pragma unroll
            for (int j = 0; j < 4; ++j)
                asm("mov.b64 {%0,%1}, %2;" : "=f"(o[2 * j]), "=f"(o[2 * j + 1]) : "l"(acc[r][j]));
            float* p = &g_h1[(size_t)row * HID_C + tx8];
            *(float4*)p       = make_float4(o[0], o[1], o[2], o[3]);
            *(float4*)(p + 4) = make_float4(o[4], o[5], o[6], o[7]);
        }
    }
}

// ---------------- aggregate layer 1: o1 = b1 + dinv^2*h1[self] + sum w*h1[src]
__global__ void __launch_bounds__(256) k_agg1(const float* __restrict__ b1) {
    int node = blockIdx.x * 8 + (threadIdx.x >> 5);
    if (node >= N_NODES) return;
    int lane = threadIdx.x & 31;
    int beg = g_rp[node], end = g_rp[node + 1];
    float d = g_dinv[node];
    float dd = d * d;
    float2 acc = *(const float2*)&g_h1[(size_t)node * HID_C + lane * 2];
    float2 bb  = *(const float2*)&b1[lane * 2];
    acc.x = bb.x + acc.x * dd;
    acc.y = bb.y + acc.y * dd;
    int j = beg;
    for (; j + 1 < end; j += 2) {
        float2 p0 = g_epk[j], p1 = g_epk[j + 1];
        int s0 = __float_as_int(p0.x), s1 = __float_as_int(p1.x);
        float2 v0 = *(const float2*)&g_h1[(size_t)s0 * HID_C + lane * 2];
        float2 v1 = *(const float2*)&g_h1[(size_t)s1 * HID_C + lane * 2];
        acc.x += p0.y * v0.x; acc.y += p0.y * v0.y;
        acc.x += p1.y * v1.x; acc.y += p1.y * v1.y;
    }
    if (j < end) {
        float2 p0 = g_epk[j];
        int s0 = __float_as_int(p0.x);
        float2 v0 = *(const float2*)&g_h1[(size_t)s0 * HID_C + lane * 2];
        acc.x += p0.y * v0.x; acc.y += p0.y * v0.y;
    }
    *(float2*)&g_o1[(size_t)node * HID_C + lane * 2] = acc;
}

// ---------------- GEMM2: h2[N,32] = relu(o1)[N,64] @ W2[64,32] -----------
__global__ void __launch_bounds__(256) k_gemm2(const float* __restrict__ W) {
    __shared__ float xs[64 * 64];
    __shared__ float ws[64 * 32];
    const int tid  = threadIdx.x;
    const int row0 = blockIdx.x * 64;

    const float4* Wv  = (const float4*)W;
    float4*       wsv = (float4*)ws;
#pragma unroll
    for (int i = 0; i < 2; ++i) wsv[tid + i * 256] = Wv[tid + i * 256];

    int nrows = N_NODES - row0; if (nrows > 64) nrows = 64;
    const float4* xv  = (const float4*)(g_o1 + (size_t)row0 * HID_C);
    float4*       xsv = (float4*)xs;
    for (int i = tid; i < nrows * 16; i += 256) {
        float4 v = xv[i];
        v.x = fmaxf(v.x, 0.f); v.y = fmaxf(v.y, 0.f);
        v.z = fmaxf(v.z, 0.f); v.w = fmaxf(v.w, 0.f);
        xsv[i] = v;
    }
    __syncthreads();

    const int tx = tid & 7;
    const int ty = tid >> 3;
    const int c  = tx * 4;
    float acc[2][4] = {};
#pragma unroll 4
    for (int k = 0; k < 64; ++k) {
        float4 b = *(const float4*)&ws[k * 32 + c];
#pragma unroll
        for (int i = 0; i < 2; ++i) {
            float a = xs[(ty * 2 + i) * 64 + k];
            acc[i][0] += a * b.x; acc[i][1] += a * b.y;
            acc[i][2] += a * b.z; acc[i][3] += a * b.w;
        }
    }
#pragma unroll
    for (int i = 0; i < 2; ++i) {
        int r = row0 + ty * 2 + i;
        if (r < N_NODES)
            *(float4*)&g_h2[(size_t)r * OUT_C + c] =
                make_float4(acc[i][0], acc[i][1], acc[i][2], acc[i][3]);
    }
}

// ---------------- aggregate layer 2 -> out -------------------------------
__global__ void __launch_bounds__(256) k_agg2(const float* __restrict__ b2,
                                              float* __restrict__ out) {
    int node = blockIdx.x * 8 + (threadIdx.x >> 5);
    if (node >= N_NODES) return;
    int lane = threadIdx.x & 31;
    int beg = g_rp[node], end = g_rp[node + 1];
    float d = g_dinv[node];
    float dd = d * d;
    float acc = b2[lane] + g_h2[(size_t)node * OUT_C + lane] * dd;
    int j = beg;
    for (; j + 1 < end; j += 2) {
        float2 p0 = g_epk[j], p1 = g_epk[j + 1];
        int s0 = __float_as_int(p0.x), s1 = __float_as_int(p1.x);
        float v0 = g_h2[(size_t)s0 * OUT_C + lane];
        float v1 = g_h2[(size_t)s1 * OUT_C + lane];
        acc += p0.y * v0 + p1.y * v1;
    }
    if (j < end) {
        float2 p0 = g_epk[j];
        int s0 = __float_as_int(p0.x);
        acc += p0.y * g_h2[(size_t)s0 * OUT_C + lane];
    }
    out[(size_t)node * OUT_C + lane] = acc;
}

// ---------------- launch -------------------------------------------------
extern "C" void kernel_launch(void* const* d_in, const int* in_sizes, int n_in,
                              void* d_out, int out_size) {
    const float* x  = (const float*)d_in[0];
    const int*   ei = (const int*)  d_in[1];
    const float* W1 = (const float*)d_in[2];
    const float* b1 = (const float*)d_in[3];
    const float* W2 = (const float*)d_in[4];
    const float* b2 = (const float*)d_in[5];
    float*       out = (float*)d_out;

    const int E   = in_sizes[1] / 2;
    const int* src = ei;
    const int* dst = ei + E;

    // CSR build + norms
    k_zero <<<(N_NODES + 255) / 256, 256>>>();
    k_count<<<(E + 255) / 256, 256>>>(dst, E);
    k_dinv <<<(N_NODES + 255) / 256, 256>>>();
    k_scan1<<<NB_SCAN, 256>>>();
    k_scan2<<<1, 512>>>();
    k_scan3<<<(N_NODES + 255) / 256, 256>>>(E);
    k_fill <<<(E + 255) / 256, 256>>>(src, dst, E);

    // layer 1
    k_gemm1<<<(N_NODES + 127) / 128, 256>>>(x, W1);
    k_agg1 <<<(N_NODES + 7) / 8, 256>>>(b1);

    // layer 2
    k_gemm2<<<(N_NODES + 63) / 64, 256>>>(W2);
    k_agg2 <<<(N_NODES + 7) / 8, 256>>>(b2, out);
}

// round 3
// speedup vs baseline: 1.4185x; 1.1125x over previous
#include <cuda_runtime.h>
#include <cuda_fp16.h>
#include <cstdint>

#define N_NODES 100000
#define IN_C    128
#define HID_C   64
#define OUT_C   32
#define E_MAX   1600000
#define NB_SCAN ((N_NODES + 255) / 256)   // 391

// ---------------- scratch ----------------
__device__ float g_dinv[N_NODES];
__device__ int   g_cnt[N_NODES];
__device__ int   g_rp[N_NODES + 1];
__device__ int   g_wptr[N_NODES];
__device__ int   g_bsum[NB_SCAN];
__device__ float2 g_epk[E_MAX];                          // (src bits, weight)
__device__ unsigned g_h1h[(size_t)N_NODES * 32];         // h1 as fp16x2, 64 ch
__device__ float    g_o1[(size_t)N_NODES * HID_C];       // aggregated layer-1 (f32)
__device__ unsigned g_h2h[(size_t)N_NODES * 16];         // h2 as fp16x2, 32 ch

// ---------------- degree / CSR ----------------
__global__ void k_zero() {
    int i = blockIdx.x * blockDim.x + threadIdx.x;
    if (i < N_NODES) g_cnt[i] = 0;
}

__global__ void k_count(const int* __restrict__ dst, int E) {
    int i = blockIdx.x * blockDim.x + threadIdx.x;
    if (i < E) atomicAdd(&g_cnt[dst[i]], 1);
}

// scan block + compute dinv
__global__ void k_scan1() {
    __shared__ int sh[256];
    int t = threadIdx.x;
    int i = blockIdx.x * 256 + t;
    int v = (i < N_NODES) ? g_cnt[i] : 0;
    if (i < N_NODES) g_dinv[i] = rsqrtf(1.0f + (float)v);
    sh[t] = v;
    __syncthreads();
#pragma unroll
    for (int off = 1; off < 256; off <<= 1) {
        int x = (t >= off) ? sh[t - off] : 0;
        __syncthreads();
        sh[t] += x;
        __syncthreads();
    }
    if (i < N_NODES) g_rp[i] = sh[t] - v;
    if (t == 255) g_bsum[blockIdx.x] = sh[255];
}

__global__ void k_scan2() {
    __shared__ int sh[512];
    int t = threadIdx.x;
    int v = (t < NB_SCAN) ? g_bsum[t] : 0;
    sh[t] = v;
    __syncthreads();
#pragma unroll
    for (int off = 1; off < 512; off <<= 1) {
        int x = (t >= off) ? sh[t - off] : 0;
        __syncthreads();
        sh[t] += x;
        __syncthreads();
    }
    if (t < NB_SCAN) g_bsum[t] = sh[t] - v;
}

__global__ void k_scan3(int E) {
    int i = blockIdx.x * blockDim.x + threadIdx.x;
    if (i < N_NODES) {
        int v = g_rp[i] + g_bsum[i >> 8];
        g_rp[i]   = v;
        g_wptr[i] = v;
    }
    if (i == 0) g_rp[N_NODES] = E;
}

__global__ void k_fill(const int* __restrict__ src, const int* __restrict__ dst, int E) {
    int e = blockIdx.x * blockDim.x + threadIdx.x;
    if (e >= E) return;
    int s = src[e], d = dst[e];
    int pos = atomicAdd(&g_wptr[d], 1);
    g_epk[pos] = make_float2(__int_as_float(s), g_dinv[s] * g_dinv[d]);
}

// ---------------- GEMM1: h1[N,64] = x[N,128] @ W1[128,64] -> fp16 --------
#define XT_STRIDE 132
__global__ void __launch_bounds__(256) k_gemm1(const float* __restrict__ x,
                                               const float* __restrict__ W) {
    __shared__ float xs_t[32 * XT_STRIDE];
    __shared__ float ws[32 * 64];
    const int t    = threadIdx.x;
    const int row0 = blockIdx.x * 128;
    const int tx8  = (t & 7) * 8;
    const int ty4  = (t >> 3) * 4;

    unsigned long long acc[4][4];
#pragma unroll
    for (int r = 0; r < 4; ++r)
#pragma unroll
        for (int j = 0; j < 4; ++j) acc[r][j] = 0ull;

    for (int kc = 0; kc < 128; kc += 32) {
        __syncthreads();
        {
            const float4* Wv = (const float4*)(W + kc * 64);
            float4* wsv = (float4*)ws;
            wsv[t]       = Wv[t];
            wsv[t + 256] = Wv[t + 256];
        }
#pragma unroll
        for (int i = 0; i < 4; ++i) {
            int idx = t + i * 256;
            int r = idx >> 3;
            int q = idx & 7;
            float4 v;
            if (row0 + r < N_NODES)
                v = *(const float4*)(x + (size_t)(row0 + r) * IN_C + kc + q * 4);
            else
                v = make_float4(0.f, 0.f, 0.f, 0.f);
            xs_t[(q * 4 + 0) * XT_STRIDE + r] = v.x;
            xs_t[(q * 4 + 1) * XT_STRIDE + r] = v.y;
            xs_t[(q * 4 + 2) * XT_STRIDE + r] = v.z;
            xs_t[(q * 4 + 3) * XT_STRIDE + r] = v.w;
        }
        __syncthreads();

#pragma unroll 8
        for (int k = 0; k < 32; ++k) {
            float4 av = *(const float4*)&xs_t[k * XT_STRIDE + ty4];
            ulonglong2 b0 = *(const ulonglong2*)&ws[k * 64 + tx8];
            ulonglong2 b1 = *(const ulonglong2*)&ws[k * 64 + tx8 + 4];
            unsigned long long pa[4];
            asm("mov.b64 %0, {%1,%1};" : "=l"(pa[0]) : "f"(av.x));
            asm("mov.b64 %0, {%1,%1};" : "=l"(pa[1]) : "f"(av.y));
            asm("mov.b64 %0, {%1,%1};" : "=l"(pa[2]) : "f"(av.z));
            asm("mov.b64 %0, {%1,%1};" : "=l"(pa[3]) : "f"(av.w));
#pragma unroll
            for (int r = 0; r < 4; ++r) {
                asm("fma.rn.f32x2 %0, %1, %2, %0;" : "+l"(acc[r][0]) : "l"(pa[r]), "l"(b0.x));
                asm("fma.rn.f32x2 %0, %1, %2, %0;" : "+l"(acc[r][1]) : "l"(pa[r]), "l"(b0.y));
                asm("fma.rn.f32x2 %0, %1, %2, %0;" : "+l"(acc[r][2]) : "l"(pa[r]), "l"(b1.x));
                asm("fma.rn.f32x2 %0, %1, %2, %0;" : "+l"(acc[r][3]) : "l"(pa[r]), "l"(b1.y));
            }
        }
    }

#pragma unroll
    for (int r = 0; r < 4; ++r) {
        int row = row0 + ty4 + r;
        if (row < N_NODES) {
            float o[8];
#pragma unroll
            for (int j = 0; j < 4; ++j)
                asm("mov.b64 {%0,%1}, %2;" : "=f"(o[2 * j]), "=f"(o[2 * j + 1]) : "l"(acc[r][j]));
            unsigned u[4];
#pragma unroll
            for (int j = 0; j < 4; ++j) {
                __half2 hh = __floats2half2_rn(o[2 * j], o[2 * j + 1]);
                u[j] = *(unsigned*)&hh;
            }
            *(uint4*)&g_h1h[(size_t)row * 32 + (t & 7) * 4] =
                make_uint4(u[0], u[1], u[2], u[3]);
        }
    }
}

// ---------------- aggregate layer 1 (fp16 gather, f32 accum) -------------
__global__ void __launch_bounds__(256) k_agg1(const float* __restrict__ b1) {
    int node = blockIdx.x * 8 + (threadIdx.x >> 5);
    if (node >= N_NODES) return;
    int lane = threadIdx.x & 31;
    int beg = g_rp[node], end = g_rp[node + 1];
    float d = g_dinv[node];
    float dd = d * d;

    unsigned sp = g_h1h[(size_t)node * 32 + lane];
    float2 sv = __half22float2(*(__half2*)&sp);
    float2 bb = *(const float2*)&b1[lane * 2];
    float ax = bb.x + sv.x * dd;
    float ay = bb.y + sv.y * dd;

    int j = beg;
    for (; j + 3 < end; j += 4) {
        float2 p0 = g_epk[j],     p1 = g_epk[j + 1];
        float2 p2 = g_epk[j + 2], p3 = g_epk[j + 3];
        unsigned v0 = g_h1h[(size_t)__float_as_int(p0.x) * 32 + lane];
        unsigned v1 = g_h1h[(size_t)__float_as_int(p1.x) * 32 + lane];
        unsigned v2 = g_h1h[(size_t)__float_as_int(p2.x) * 32 + lane];
        unsigned v3 = g_h1h[(size_t)__float_as_int(p3.x) * 32 + lane];
        float2 f0 = __half22float2(*(__half2*)&v0);
        float2 f1 = __half22float2(*(__half2*)&v1);
        float2 f2 = __half22float2(*(__half2*)&v2);
        float2 f3 = __half22float2(*(__half2*)&v3);
        ax += p0.y * f0.x + p1.y * f1.x + p2.y * f2.x + p3.y * f3.x;
        ay += p0.y * f0.y + p1.y * f1.y + p2.y * f2.y + p3.y * f3.y;
    }
    for (; j < end; ++j) {
        float2 p0 = g_epk[j];
        unsigned v0 = g_h1h[(size_t)__float_as_int(p0.x) * 32 + lane];
        float2 f0 = __half22float2(*(__half2*)&v0);
        ax += p0.y * f0.x;
        ay += p0.y * f0.y;
    }
    *(float2*)&g_o1[(size_t)node * HID_C + lane * 2] = make_float2(ax, ay);
}

// ---------------- GEMM2: h2[N,32] = relu(o1)[N,64] @ W2[64,32] -> fp16 ---
__global__ void __launch_bounds__(256) k_gemm2(const float* __restrict__ W) {
    __shared__ float xs[64 * 64];
    __shared__ float ws[64 * 32];
    const int tid  = threadIdx.x;
    const int row0 = blockIdx.x * 64;

    const float4* Wv  = (const float4*)W;
    float4*       wsv = (float4*)ws;
#pragma unroll
    for (int i = 0; i < 2; ++i) wsv[tid + i * 256] = Wv[tid + i * 256];

    int nrows = N_NODES - row0; if (nrows > 64) nrows = 64;
    const float4* xv  = (const float4*)(g_o1 + (size_t)row0 * HID_C);
    float4*       xsv = (float4*)xs;
    for (int i = tid; i < nrows * 16; i += 256) {
        float4 v = xv[i];
        v.x = fmaxf(v.x, 0.f); v.y = fmaxf(v.y, 0.f);
        v.z = fmaxf(v.z, 0.f); v.w = fmaxf(v.w, 0.f);
        xsv[i] = v;
    }
    __syncthreads();

    const int tx = tid & 7;
    const int ty = tid >> 3;
    const int c  = tx * 4;
    float acc[2][4] = {};
#pragma unroll 4
    for (int k = 0; k < 64; ++k) {
        float4 b = *(const float4*)&ws[k * 32 + c];
#pragma unroll
        for (int i = 0; i < 2; ++i) {
            float a = xs[(ty * 2 + i) * 64 + k];
            acc[i][0] += a * b.x; acc[i][1] += a * b.y;
            acc[i][2] += a * b.z; acc[i][3] += a * b.w;
        }
    }
#pragma unroll
    for (int i = 0; i < 2; ++i) {
        int r = row0 + ty * 2 + i;
        if (r < N_NODES) {
            __half2 h0 = __floats2half2_rn(acc[i][0], acc[i][1]);
            __half2 h1 = __floats2half2_rn(acc[i][2], acc[i][3]);
            *(uint2*)&g_h2h[(size_t)r * 16 + tx * 2] =
                make_uint2(*(unsigned*)&h0, *(unsigned*)&h1);
        }
    }
}

// ---------------- aggregate layer 2 -> out (2 edges/warp-iter) -----------
__global__ void __launch_bounds__(256) k_agg2(const float* __restrict__ b2,
                                              float* __restrict__ out) {
    int node = blockIdx.x * 8 + (threadIdx.x >> 5);
    if (node >= N_NODES) return;
    int lane = threadIdx.x & 31;
    int c  = lane & 15;    // channel pair
    int eo = lane >> 4;    // edge offset within pair

    int beg = g_rp[node], end = g_rp[node + 1];
    float ax = 0.f, ay = 0.f;

    int j = beg + eo;
    for (; j + 1 < end; j += 4) {      // each half-warp does j, j+2
        float2 p0 = g_epk[j], p1 = g_epk[j + 2 <= end - 1 ? j + 2 : j]; // guarded below
        // note: the guarded form above is replaced by explicit checks:
        unsigned v0 = g_h2h[(size_t)__float_as_int(p0.x) * 16 + c];
        float2 f0 = __half22float2(*(__half2*)&v0);
        ax += p0.y * f0.x; ay += p0.y * f0.y;
        if (j + 2 < end) {
            float2 p1b = g_epk[j + 2];
            unsigned v1 = g_h2h[(size_t)__float_as_int(p1b.x) * 16 + c];
            float2 f1 = __half22float2(*(__half2*)&v1);
            ax += p1b.y * f1.x; ay += p1b.y * f1.y;
        }
        (void)p1;
        j += 0;
        break;  // structured loop below instead
    }
    // clean simple loop (stride 2 per half-warp)
    ax = 0.f; ay = 0.f;
    for (j = beg + eo; j < end; j += 2) {
        float2 p = g_epk[j];
        unsigned v = g_h2h[(size_t)__float_as_int(p.x) * 16 + c];
        float2 f = __half22float2(*(__half2*)&v);
        ax += p.y * f.x; ay += p.y * f.y;
    }

    // combine the two half-warps
    ax += __shfl_xor_sync(0xffffffffu, ax, 16);
    ay += __shfl_xor_sync(0xffffffffu, ay, 16);

    if (eo == 0) {
        float d = g_dinv[node];
        float dd = d * d;
        unsigned sp = g_h2h[(size_t)node * 16 + c];
        float2 sv = __half22float2(*(__half2*)&sp);
        float2 bb = *(const float2*)&b2[c * 2];
        ax += bb.x + sv.x * dd;
        ay += bb.y + sv.y * dd;
        *(float2*)&out[(size_t)node * OUT_C + c * 2] = make_float2(ax, ay);
    }
}

// ---------------- launch -------------------------------------------------
extern "C" void kernel_launch(void* const* d_in, const int* in_sizes, int n_in,
                              void* d_out, int out_size) {
    const float* x  = (const float*)d_in[0];
    const int*   ei = (const int*)  d_in[1];
    const float* W1 = (const float*)d_in[2];
    const float* b1 = (const float*)d_in[3];
    const float* W2 = (const float*)d_in[4];
    const float* b2 = (const float*)d_in[5];
    float*       out = (float*)d_out;

    const int E   = in_sizes[1] / 2;
    const int* src = ei;
    const int* dst = ei + E;

    k_zero <<<(N_NODES + 255) / 256, 256>>>();
    k_count<<<(E + 255) / 256, 256>>>(dst, E);
    k_scan1<<<NB_SCAN, 256>>>();
    k_scan2<<<1, 512>>>();
    k_scan3<<<(N_NODES + 255) / 256, 256>>>(E);
    k_fill <<<(E + 255) / 256, 256>>>(src, dst, E);

    k_gemm1<<<(N_NODES + 127) / 128, 256>>>(x, W1);
    k_agg1 <<<(N_NODES + 7) / 8, 256>>>(b1);

    k_gemm2<<<(N_NODES + 63) / 64, 256>>>(W2);
    k_agg2 <<<(N_NODES + 7) / 8, 256>>>(b2, out);
}